// round 5
// baseline (speedup 1.0000x reference)
#include <cuda_runtime.h>
#include <cstdint>
#include <cstddef>

// Problem constants (fixed by the dataset)
#define NBUG   200000
#define NUSER  100000
#define INDIM  256
#define HIDC   128
#define OUTC   64
#define NCLS_C 128
#define EMAX   2000000

// ----------------------------------------------------------------------------
// Scratch (static __device__ globals — the allowed workaround for no-alloc rule)
// ----------------------------------------------------------------------------
__device__ float g_hb1[(size_t)NBUG * HIDC];    // layer-1 bug projection
__device__ float g_hu1[(size_t)NUSER * HIDC];   // layer-1 user projection
__device__ float g_ob [(size_t)NBUG * HIDC];    // relu(z_bug1)  (= elu'd, since elu∘relu = relu)
__device__ float g_ou [(size_t)NUSER * HIDC];   // relu(z_user1)
__device__ float g_hb2[(size_t)NBUG * OUTC];    // layer-2 bug projection
__device__ float g_hu2[(size_t)NUSER * OUTC];   // layer-2 user projection
__device__ float g_zb2[(size_t)NBUG * OUTC];    // relu(z_bug2)

__device__ float g_s_bu_src[NBUG * 2];
__device__ float g_s_ub_dst[NBUG * 2];
__device__ float g_s_bu_dst[NUSER * 2];
__device__ float g_s_ub_src[NUSER * 2];
__device__ float g_s2_src[NUSER];
__device__ float g_s2_dst[NBUG];

__device__ int g_col_u[EMAX];     // CSR (dst = user): src indices in segment order
__device__ int g_col_b[EMAX];     // CSR (dst = bug)
__device__ int g_deg_u[NUSER];
__device__ int g_deg_b[NBUG];
__device__ int g_rowptr_u[NUSER + 1];
__device__ int g_rowptr_b[NBUG + 1];
__device__ int g_cur_u[NUSER];
__device__ int g_cur_b[NBUG];
__device__ int g_bsum[1024];
__device__ int g_boff[1024];

// ----------------------------------------------------------------------------
// GEMM: C[M,N] = A[M,K] @ W[K,N] + bias.  BM=128 BN=64 BK=16, 256 thr, 8x4 tile
// K multiple of 16, N multiple of 64 (all shapes here satisfy this).
// ----------------------------------------------------------------------------
__global__ __launch_bounds__(256)
void sgemm_kernel(const float* __restrict__ A, const float* __restrict__ W,
                  const float* __restrict__ bias, float* __restrict__ C,
                  int M, int K, int N)
{
    __shared__ float As[16][128];
    __shared__ float Ws[16][64];
    const int tid = threadIdx.x;
    const int m0 = blockIdx.x * 128;
    const int n0 = blockIdx.y * 64;
    const int tx = tid & 15;     // 16 col groups of 4
    const int ty = tid >> 4;     // 16 row groups of 8

    float acc[8][4];
#pragma unroll
    for (int i = 0; i < 8; i++)
#pragma unroll
        for (int j = 0; j < 4; j++) acc[i][j] = 0.f;

    const int ar = tid >> 1;          // 0..127
    const int ak = (tid & 1) * 8;     // 0 or 8
    const int wr = tid >> 4;          // 0..15 (k)
    const int wc = (tid & 15) * 4;    // 0..60

    const bool arow_ok = (m0 + ar) < M;
    const float* Aptr = A + (size_t)(m0 + ar) * K + ak;

    for (int k0 = 0; k0 < K; k0 += 16) {
        float4 a0 = make_float4(0.f, 0.f, 0.f, 0.f);
        float4 a1 = a0;
        if (arow_ok) {
            a0 = *(const float4*)(Aptr + k0);
            a1 = *(const float4*)(Aptr + k0 + 4);
        }
        float4 w0 = *(const float4*)(W + (size_t)(k0 + wr) * N + n0 + wc);
        __syncthreads();
        As[ak + 0][ar] = a0.x; As[ak + 1][ar] = a0.y;
        As[ak + 2][ar] = a0.z; As[ak + 3][ar] = a0.w;
        As[ak + 4][ar] = a1.x; As[ak + 5][ar] = a1.y;
        As[ak + 6][ar] = a1.z; As[ak + 7][ar] = a1.w;
        *(float4*)&Ws[wr][wc] = w0;
        __syncthreads();

#pragma unroll
        for (int kk = 0; kk < 16; kk++) {
            float4 x0 = *(const float4*)&As[kk][ty * 8];
            float4 x1 = *(const float4*)&As[kk][ty * 8 + 4];
            float4 wv = *(const float4*)&Ws[kk][tx * 4];
            float xa[8] = {x0.x, x0.y, x0.z, x0.w, x1.x, x1.y, x1.z, x1.w};
            float wb[4] = {wv.x, wv.y, wv.z, wv.w};
#pragma unroll
            for (int i = 0; i < 8; i++)
#pragma unroll
                for (int j = 0; j < 4; j++)
                    acc[i][j] = fmaf(xa[i], wb[j], acc[i][j]);
        }
    }

    float4 bv = *(const float4*)(bias + n0 + tx * 4);
#pragma unroll
    for (int i = 0; i < 8; i++) {
        int row = m0 + ty * 8 + i;
        if (row < M) {
            float4 o;
            o.x = acc[i][0] + bv.x;
            o.y = acc[i][1] + bv.y;
            o.z = acc[i][2] + bv.z;
            o.w = acc[i][3] + bv.w;
            *(float4*)(C + (size_t)row * N + n0 + tx * 4) = o;
        }
    }
}

// ----------------------------------------------------------------------------
// Per-node attention scores: sA[i,h] = h[i,h,:]·attA[h,:], same for attB (opt)
// ----------------------------------------------------------------------------
template <int C, int H>
__global__ __launch_bounds__(256)
void scores_kernel(const float* __restrict__ h,
                   const float* __restrict__ attA, const float* __restrict__ attB,
                   float* __restrict__ sA, float* __restrict__ sB, int n)
{
    const int warp = (int)((blockIdx.x * (unsigned)blockDim.x + threadIdx.x) >> 5);
    const int lane = threadIdx.x & 31;
    if (warp >= n) return;
    constexpr int LANES = C / 4;
    constexpr int D4 = (C / H) / 4;   // lanes per head (16 here)
    const bool hasB = (sB != nullptr);

    float pa = 0.f, pb = 0.f;
    if (lane < LANES) {
        float4 hv = *(const float4*)(h + (size_t)warp * C + lane * 4);
        float4 aa = *(const float4*)(attA + lane * 4);
        pa = hv.x * aa.x + hv.y * aa.y + hv.z * aa.z + hv.w * aa.w;
        if (hasB) {
            float4 ab = *(const float4*)(attB + lane * 4);
            pb = hv.x * ab.x + hv.y * ab.y + hv.z * ab.z + hv.w * ab.w;
        }
    }
#pragma unroll
    for (int off = D4 / 2; off >= 1; off >>= 1) {
        pa += __shfl_down_sync(0xffffffffu, pa, off);
        pb += __shfl_down_sync(0xffffffffu, pb, off);
    }
    if (lane < LANES && (lane % D4) == 0) {
        int hh = lane / D4;
        sA[warp * H + hh] = pa;
        if (hasB) sB[warp * H + hh] = pb;
    }
}

// ----------------------------------------------------------------------------
// CSR build helpers
// ----------------------------------------------------------------------------
__global__ void hist_kernel(const int* __restrict__ dst, int E, int* __restrict__ deg)
{
    int e = blockIdx.x * blockDim.x + threadIdx.x;
    if (e < E) atomicAdd(&deg[dst[e]], 1);
}

__global__ void scatter_kernel(const int* __restrict__ src, const int* __restrict__ dst,
                               int* __restrict__ cur, int* __restrict__ col, int E)
{
    int e = blockIdx.x * blockDim.x + threadIdx.x;
    if (e < E) {
        int p = atomicAdd(&cur[dst[e]], 1);
        col[p] = src[e];
    }
}

__global__ __launch_bounds__(256)
void scan1_kernel(const int* __restrict__ in, int* __restrict__ out,
                  int* __restrict__ bsum, int n)
{
    __shared__ int sh[256];
    const int t = threadIdx.x;
    const int base = blockIdx.x * 1024 + t * 4;
    int v0 = (base + 0 < n) ? in[base + 0] : 0;
    int v1 = (base + 1 < n) ? in[base + 1] : 0;
    int v2 = (base + 2 < n) ? in[base + 2] : 0;
    int v3 = (base + 3 < n) ? in[base + 3] : 0;
    int tsum = v0 + v1 + v2 + v3;
    sh[t] = tsum;
    __syncthreads();
#pragma unroll
    for (int off = 1; off < 256; off <<= 1) {
        int x = (t >= off) ? sh[t - off] : 0;
        __syncthreads();
        sh[t] += x;
        __syncthreads();
    }
    if (bsum != nullptr && t == 255) bsum[blockIdx.x] = sh[255];
    int run = sh[t] - tsum;  // exclusive prefix
    if (base + 0 < n) out[base + 0] = run; run += v0;
    if (base + 1 < n) out[base + 1] = run; run += v1;
    if (base + 2 < n) out[base + 2] = run; run += v2;
    if (base + 3 < n) out[base + 3] = run;
}

__global__ __launch_bounds__(256)
void scan3_kernel(int* __restrict__ out, const int* __restrict__ boff, int n)
{
    const int base = blockIdx.x * 1024 + threadIdx.x * 4;
    int add = boff[blockIdx.x];
#pragma unroll
    for (int i = 0; i < 4; i++)
        if (base + i < n) out[base + i] += add;
}

__global__ void set_tail_kernel(int* p, int idx, int val) { p[idx] = val; }

// ----------------------------------------------------------------------------
// GAT segment-softmax aggregation, one warp per destination node.
// Phase 1: warp-online softmax stats; Phase 2: weighted float-vector gather.
// out = relu(segment_sum(alpha * h_src))
// ----------------------------------------------------------------------------
template <int C, int H>
__global__ __launch_bounds__(256)
void agg_kernel(const float* __restrict__ hsrc, const float* __restrict__ ssrc,
                const float* __restrict__ sdst, const int* __restrict__ rowptr,
                const int* __restrict__ col, float* __restrict__ out, int ndst)
{
    const int warp = (int)((blockIdx.x * (unsigned)blockDim.x + threadIdx.x) >> 5);
    const int lane = threadIdx.x & 31;
    if (warp >= ndst) return;
    constexpr int VEC = C / 32;   // 4 (C=128) or 2 (C=64)
    constexpr int D = C / H;

    const int start = rowptr[warp];
    const int end   = rowptr[warp + 1];

    float sd[H];
#pragma unroll
    for (int h = 0; h < H; h++) sd[h] = sdst[warp * H + h];

    // ---- phase 1: per-lane online (m,z), then warp merge ----
    float m[H], z[H];
#pragma unroll
    for (int h = 0; h < H; h++) { m[h] = -1e30f; z[h] = 0.f; }

    for (int e = start + lane; e < end; e += 32) {
        int s = col[e];
#pragma unroll
        for (int h = 0; h < H; h++) {
            float x = ssrc[s * H + h] + sd[h];
            float a = fmaxf(x, 0.2f * x);          // leaky_relu(0.2)
            if (a > m[h]) { z[h] = z[h] * __expf(m[h] - a) + 1.0f; m[h] = a; }
            else          { z[h] += __expf(a - m[h]); }
        }
    }
#pragma unroll
    for (int h = 0; h < H; h++) {
#pragma unroll
        for (int off = 16; off >= 1; off >>= 1) {
            float mo = __shfl_xor_sync(0xffffffffu, m[h], off);
            float zo = __shfl_xor_sync(0xffffffffu, z[h], off);
            float mn = fmaxf(m[h], mo);
            z[h] = z[h] * __expf(m[h] - mn) + zo * __expf(mo - mn);
            m[h] = mn;
        }
    }

    // ---- phase 2: weighted gather-accumulate ----
    const int hl = (lane * VEC) / D;
    const float mh  = m[hl];
    const float inv = 1.0f / fmaxf(z[hl], 1e-16f);
    const float sdh = sd[hl];

    float acc[VEC];
#pragma unroll
    for (int v = 0; v < VEC; v++) acc[v] = 0.f;

    for (int e = start; e < end; e++) {
        int s = col[e];   // same address across warp -> broadcast
        float x = ssrc[s * H + hl] + sdh;
        float a = fmaxf(x, 0.2f * x);
        float w = __expf(a - mh) * inv;
        const float* row = hsrc + (size_t)s * C + lane * VEC;
        if (VEC == 4) {
            float4 r = *(const float4*)row;
            acc[0] = fmaf(w, r.x, acc[0]);
            acc[1] = fmaf(w, r.y, acc[1]);
            acc[2] = fmaf(w, r.z, acc[2]);
            acc[3] = fmaf(w, r.w, acc[3]);
        } else {
            float2 r = *(const float2*)row;
            acc[0] = fmaf(w, r.x, acc[0]);
            acc[1] = fmaf(w, r.y, acc[1]);
        }
    }

    float* o = out + (size_t)warp * C + lane * VEC;
    if (VEC == 4) {
        float4 r;
        r.x = fmaxf(acc[0], 0.f); r.y = fmaxf(acc[1], 0.f);
        r.z = fmaxf(acc[2], 0.f); r.w = fmaxf(acc[3], 0.f);
        *(float4*)o = r;
    } else {
        float2 r;
        r.x = fmaxf(acc[0], 0.f); r.y = fmaxf(acc[1], 0.f);
        *(float2*)o = r;
    }
}

// ----------------------------------------------------------------------------
// Host launcher
// ----------------------------------------------------------------------------
static inline void* sym_addr(const void* sym)
{
    void* p = nullptr;
    cudaGetSymbolAddress(&p, sym);
    return p;
}

static void run_scan(int* deg, int* rowptr, int n, int total)
{
    int* bsum = (int*)sym_addr(g_bsum);
    int* boff = (int*)sym_addr(g_boff);
    int nb = (n + 1023) / 1024;
    scan1_kernel<<<nb, 256>>>(deg, rowptr, bsum, n);
    scan1_kernel<<<1, 256>>>(bsum, boff, nullptr, nb);
    scan3_kernel<<<nb, 256>>>(rowptr, boff, n);
    set_tail_kernel<<<1, 1>>>(rowptr, n, total);
}

extern "C" void kernel_launch(void* const* d_in, const int* in_sizes, int n_in,
                              void* d_out, int out_size)
{
    const float* xb      = (const float*)d_in[0];
    const float* xu      = (const float*)d_in[1];
    const int*   ebu_src = (const int*)d_in[2];
    const int*   ebu_dst = (const int*)d_in[3];
    const int*   eub_src = (const int*)d_in[4];
    const int*   eub_dst = (const int*)d_in[5];
    const float* w1_bug  = (const float*)d_in[6];
    const float* b1_bug  = (const float*)d_in[7];
    const float* w1_user = (const float*)d_in[8];
    const float* b1_user = (const float*)d_in[9];
    const float* a1_bu_s = (const float*)d_in[10];
    const float* a1_bu_d = (const float*)d_in[11];
    const float* a1_ub_s = (const float*)d_in[12];
    const float* a1_ub_d = (const float*)d_in[13];
    // d_in[14..16]: k1_w, k1_b, q1  — semantic attention over 1 relation == identity
    const float* w2_bug  = (const float*)d_in[17];
    const float* b2_bug  = (const float*)d_in[18];
    const float* w2_user = (const float*)d_in[19];
    const float* b2_user = (const float*)d_in[20];
    // d_in[21..22]: a2_bu_*  — layer-2 user branch is dead (output discarded)
    const float* a2_ub_s = (const float*)d_in[23];
    const float* a2_ub_d = (const float*)d_in[24];
    // d_in[25..27]: k2_w, k2_b, q2 — identity
    const float* wc      = (const float*)d_in[28];
    const float* bc      = (const float*)d_in[29];

    const int E = in_sizes[2];

    float* hb1 = (float*)sym_addr(g_hb1);
    float* hu1 = (float*)sym_addr(g_hu1);
    float* ob  = (float*)sym_addr(g_ob);
    float* ou  = (float*)sym_addr(g_ou);
    float* hb2 = (float*)sym_addr(g_hb2);
    float* hu2 = (float*)sym_addr(g_hu2);
    float* zb2 = (float*)sym_addr(g_zb2);
    float* s_bu_src = (float*)sym_addr(g_s_bu_src);
    float* s_ub_dst = (float*)sym_addr(g_s_ub_dst);
    float* s_bu_dst = (float*)sym_addr(g_s_bu_dst);
    float* s_ub_src = (float*)sym_addr(g_s_ub_src);
    float* s2_src   = (float*)sym_addr(g_s2_src);
    float* s2_dst   = (float*)sym_addr(g_s2_dst);
    int* col_u = (int*)sym_addr(g_col_u);
    int* col_b = (int*)sym_addr(g_col_b);
    int* deg_u = (int*)sym_addr(g_deg_u);
    int* deg_b = (int*)sym_addr(g_deg_b);
    int* rp_u  = (int*)sym_addr(g_rowptr_u);
    int* rp_b  = (int*)sym_addr(g_rowptr_b);
    int* cur_u = (int*)sym_addr(g_cur_u);
    int* cur_b = (int*)sym_addr(g_cur_b);

    const int eg = (E + 255) / 256;

    // ---- CSR build (both directions; eub CSR reused by layer 2) ----
    cudaMemsetAsync(deg_u, 0, NUSER * sizeof(int), 0);
    cudaMemsetAsync(deg_b, 0, NBUG * sizeof(int), 0);
    hist_kernel<<<eg, 256>>>(ebu_dst, E, deg_u);
    hist_kernel<<<eg, 256>>>(eub_dst, E, deg_b);
    run_scan(deg_u, rp_u, NUSER, E);
    run_scan(deg_b, rp_b, NBUG, E);
    cudaMemcpyAsync(cur_u, rp_u, NUSER * sizeof(int), cudaMemcpyDeviceToDevice, 0);
    cudaMemcpyAsync(cur_b, rp_b, NBUG * sizeof(int), cudaMemcpyDeviceToDevice, 0);
    scatter_kernel<<<eg, 256>>>(ebu_src, ebu_dst, cur_u, col_u, E);
    scatter_kernel<<<eg, 256>>>(eub_src, eub_dst, cur_b, col_b, E);

    // ---- Layer 1 projections ----
    {
        dim3 g((NBUG + 127) / 128, HIDC / 64);
        sgemm_kernel<<<g, 256>>>(xb, w1_bug, b1_bug, hb1, NBUG, INDIM, HIDC);
    }
    {
        dim3 g((NUSER + 127) / 128, HIDC / 64);
        sgemm_kernel<<<g, 256>>>(xu, w1_user, b1_user, hu1, NUSER, INDIM, HIDC);
    }

    // ---- Layer 1 node scores (2 heads) ----
    scores_kernel<HIDC, 2><<<(NBUG + 7) / 8, 256>>>(hb1, a1_bu_s, a1_ub_d,
                                                    s_bu_src, s_ub_dst, NBUG);
    scores_kernel<HIDC, 2><<<(NUSER + 7) / 8, 256>>>(hu1, a1_ub_s, a1_bu_d,
                                                     s_ub_src, s_bu_dst, NUSER);

    // ---- Layer 1 edge attention + aggregation (fused relu; elu is a no-op after relu) ----
    agg_kernel<HIDC, 2><<<(NUSER + 7) / 8, 256>>>(hb1, s_bu_src, s_bu_dst,
                                                  rp_u, col_u, ou, NUSER);
    agg_kernel<HIDC, 2><<<(NBUG + 7) / 8, 256>>>(hu1, s_ub_src, s_ub_dst,
                                                 rp_b, col_b, ob, NBUG);

    // ---- Layer 2 projections ----
    {
        dim3 g((NBUG + 127) / 128, OUTC / 64);
        sgemm_kernel<<<g, 256>>>(ob, w2_bug, b2_bug, hb2, NBUG, HIDC, OUTC);
    }
    {
        dim3 g((NUSER + 127) / 128, OUTC / 64);
        sgemm_kernel<<<g, 256>>>(ou, w2_user, b2_user, hu2, NUSER, HIDC, OUTC);
    }

    // ---- Layer 2 scores (1 head) + user->bug aggregation only ----
    scores_kernel<OUTC, 1><<<(NUSER + 7) / 8, 256>>>(hu2, a2_ub_s, nullptr,
                                                     s2_src, nullptr, NUSER);
    scores_kernel<OUTC, 1><<<(NBUG + 7) / 8, 256>>>(hb2, a2_ub_d, nullptr,
                                                    s2_dst, nullptr, NBUG);
    agg_kernel<OUTC, 1><<<(NBUG + 7) / 8, 256>>>(hu2, s2_src, s2_dst,
                                                 rp_b, col_b, zb2, NBUG);

    // ---- Classifier ----
    {
        dim3 g((NBUG + 127) / 128, NCLS_C / 64);
        sgemm_kernel<<<g, 256>>>(zb2, wc, bc, (float*)d_out, NBUG, OUTC, NCLS_C);
    }
}